// round 16
// baseline (speedup 1.0000x reference)
#include <cuda_runtime.h>
#include <cuda_fp16.h>
#include <stdint.h>

#define NN 262144
#define NE (4*1024*1024)

typedef unsigned long long ull;

// Scratch (device globals — no allocation allowed; zero-initialized at load)
__device__ __half g_h0[NN * 16];                // layer-0 input, half, padded 9->16 (32B rows)
__device__ __half g_zl[4][NN * 32];             // per-layer PRE-BN MLP outputs, half (64B rows)
__device__ float  g_agg[NN * 32];               // gather output, fp32
__device__ float  g_stats[256];                 // per layer: [l*64+c]=sum, [l*64+32+c]=sumsq
// CSR-by-dst scratch
__device__ int g_deg[NN];                       // invariant: ZERO at kernel_launch entry
__device__ int g_off[NN + 1];
__device__ int g_pos[NN];
__device__ int g_csr[NE];
__device__ int g_bsum[256];
__device__ int g_bsum2[256];
__device__ unsigned int g_ticket;               // scan1 last-block ticket (reset in scan1)

// packed f32x2 helpers (FFMA2 is PTX-only on sm_103a)
__device__ __forceinline__ ull pk2(float a, float b) {
    ull r; asm("mov.b64 %0,{%1,%2};" : "=l"(r) : "f"(a), "f"(b)); return r;
}
__device__ __forceinline__ void upk2(ull v, float& a, float& b) {
    asm("mov.b64 {%0,%1},%2;" : "=f"(a), "=f"(b) : "l"(v));
}
__device__ __forceinline__ ull fma2(ull a, ull b, ull c) {
    ull d; asm("fma.rn.f32x2 %0,%1,%2,%3;" : "=l"(d) : "l"(a), "l"(b), "l"(c)); return d;
}

// ---------------------------------------------------------------------------
// init+count fused: build h0, zero stats, count degrees (deg==0 on entry)
// ---------------------------------------------------------------------------
__global__ void k_initcount(const float* __restrict__ x, const float* __restrict__ t,
                            const int* __restrict__ dst) {
    int i = blockIdx.x * blockDim.x + threadIdx.x;
    if (i < NN * 16) {
        int n = i >> 4, k = i & 15;
        float v = 0.f;
        if (k < 8) v = x[n * 8 + k];
        else if (k == 8) v = t[0];
        g_h0[i] = __float2half(v);
    }
    if (i < 256) g_stats[i] = 0.f;
    if (i < NE) atomicAdd(&g_deg[dst[i]], 1);
}

// ---------------------------------------------------------------------------
// scan1 with fused block-sum scan (last-block ticket)
// ---------------------------------------------------------------------------
__global__ void k_scan1() {   // 256 blocks x 1024 threads
    __shared__ int s[1024];
    int tid = threadIdx.x;
    int i = blockIdx.x * 1024 + tid;
    int v = g_deg[i];
    s[tid] = v;
    __syncthreads();
#pragma unroll
    for (int off = 1; off < 1024; off <<= 1) {
        int tv = (tid >= off) ? s[tid - off] : 0;
        __syncthreads();
        s[tid] += tv;
        __syncthreads();
    }
    g_off[i] = s[tid] - v;
    if (tid == 1023) g_bsum[blockIdx.x] = s[1023];

    __shared__ unsigned int isLast;
    __threadfence();
    __syncthreads();
    if (tid == 0) {
        unsigned int old = atomicAdd(&g_ticket, 1u);
        isLast = (old == 255u) ? 1u : 0u;
        if (isLast) g_ticket = 0u;
    }
    __syncthreads();
    if (isLast) {
        __shared__ int bs[256];
        if (tid < 256) bs[tid] = g_bsum[tid];
        __syncthreads();
#pragma unroll
        for (int off = 1; off < 256; off <<= 1) {
            int tv = (tid < 256 && tid >= off) ? bs[tid - off] : 0;
            __syncthreads();
            if (tid < 256) bs[tid] += tv;
            __syncthreads();
        }
        if (tid < 256) g_bsum2[tid] = bs[tid] - g_bsum[tid];
    }
}

__global__ void k_scan3() {
    int i = blockIdx.x * blockDim.x + threadIdx.x;
    if (i < NN) {
        int o = g_off[i] + g_bsum2[i >> 10];
        g_off[i] = o;
        g_pos[i] = o;
        g_deg[i] = 0;
    }
    if (i == 0) g_off[NN] = NE;
}

__global__ void k_fill(const int* __restrict__ src, const int* __restrict__ dst) {
    int e = blockIdx.x * blockDim.x + threadIdx.x;
    if (e >= NE) return;
    int slot = atomicAdd(&g_pos[dst[e]], 1);
    g_csr[slot] = src[e];
}

// ---------------------------------------------------------------------------
// gather (half source, optional inline BN+ReLU): chunk-per-thread,
// chunk = 8 channels = one uint4. If BN: h = max(0, z*A + B) per channel.
// ---------------------------------------------------------------------------
template<int SHIFT, int ROWH, bool BN>
__global__ void __launch_bounds__(256) k_gatherH(const __half* __restrict__ hbase,
                                                 const float* __restrict__ gamma,
                                                 const float* __restrict__ beta,
                                                 int lprev) {
    int idx = blockIdx.x * blockDim.x + threadIdx.x;
    int n = idx >> SHIFT;
    int c = idx & ((1 << SHIFT) - 1);
    if (n >= NN) return;

    float A[8], B[8];
    if (BN) {
        const float inv = 1.0f / (float)NN;
#pragma unroll
        for (int q = 0; q < 8; q++) {
            int ch = c * 8 + q;
            float mu = g_stats[lprev * 64 + ch] * inv;
            float var = g_stats[lprev * 64 + 32 + ch] * inv - mu * mu;
            float rs = rsqrtf(var + 1e-5f);
            float ga = gamma[lprev * 32 + ch];
            A[q] = rs * ga;
            B[q] = beta[lprev * 32 + ch] - mu * rs * ga;
        }
    }

    int k = g_off[n], end = g_off[n + 1];
    float a[8];
#pragma unroll
    for (int q = 0; q < 8; q++) a[q] = 0.f;

    auto accv = [&](uint4 v) {
        const __half2* h = (const __half2*)&v;
#pragma unroll
        for (int q = 0; q < 4; q++) {
            float2 f = __half22float2(h[q]);
            if (BN) {
                f.x = fmaxf(fmaf(f.x, A[2 * q + 0], B[2 * q + 0]), 0.f);
                f.y = fmaxf(fmaf(f.y, A[2 * q + 1], B[2 * q + 1]), 0.f);
            }
            a[2 * q + 0] += f.x;
            a[2 * q + 1] += f.y;
        }
    };

    for (; k + 4 <= end; k += 4) {
        int s0 = g_csr[k], s1 = g_csr[k + 1], s2 = g_csr[k + 2], s3 = g_csr[k + 3];
        uint4 v0 = *((const uint4*)(hbase + (size_t)s0 * ROWH) + c);
        uint4 v1 = *((const uint4*)(hbase + (size_t)s1 * ROWH) + c);
        uint4 v2 = *((const uint4*)(hbase + (size_t)s2 * ROWH) + c);
        uint4 v3 = *((const uint4*)(hbase + (size_t)s3 * ROWH) + c);
        accv(v0); accv(v1); accv(v2); accv(v3);
    }
    for (; k < end; k++) {
        int s0 = g_csr[k];
        uint4 v0 = *((const uint4*)(hbase + (size_t)s0 * ROWH) + c);
        accv(v0);
    }
    float* ap = g_agg + (size_t)n * 32 + c * 8;
    float4 o0; o0.x = a[0]; o0.y = a[1]; o0.z = a[2]; o0.w = a[3];
    float4 o1; o1.x = a[4]; o1.y = a[5]; o1.z = a[6]; o1.w = a[7];
    *(float4*)(ap + 0) = o0;
    *(float4*)(ap + 4) = o1;
}

// ---------------------------------------------------------------------------
// node MLP (packed f32x2) + fused BN-stats; h input optionally BN'd inline.
// Output written as HALF to g_zl[l] (full 64B row = 4 uint4).
// ---------------------------------------------------------------------------
template<int K, int KROWS, int HSTH, bool BNIN>
__global__ void __launch_bounds__(128) k_node(
    const __half* __restrict__ hprev,
    const float* __restrict__ W1, const float* __restrict__ b1,
    const float* __restrict__ W2, const float* __restrict__ b2,
    const float* __restrict__ eps,
    const float* __restrict__ gamma, const float* __restrict__ beta,
    int l)
{
    __shared__ __align__(16) float sW1[K * 32];
    __shared__ __align__(16) float sW2[32 * 32];
    __shared__ __align__(16) float sb1[32];
    __shared__ __align__(16) float sb2[32];
    __shared__ float ss2[32], sq2[32];
    __shared__ float shA[32], shB[32];
    int tid = threadIdx.x;
    for (int i = tid; i < K * 32; i += 128) {
        int k = i >> 5;
        sW1[i] = (k < KROWS) ? W1[i] : 0.f;
    }
    for (int i = tid; i < 1024; i += 128) sW2[i] = W2[i];
    if (tid < 32) {
        sb1[tid] = b1[tid]; sb2[tid] = b2[tid]; ss2[tid] = 0.f; sq2[tid] = 0.f;
        if (BNIN) {
            const float inv = 1.0f / (float)NN;
            int lp = l - 1;
            float mu = g_stats[lp * 64 + tid] * inv;
            float var = g_stats[lp * 64 + 32 + tid] * inv - mu * mu;
            float rs = rsqrtf(var + 1e-5f);
            float ga = gamma[lp * 32 + tid];
            shA[tid] = rs * ga;
            shB[tid] = beta[lp * 32 + tid] - mu * rs * ga;
        }
    }
    __syncthreads();

    int n = blockIdx.x * 128 + tid;     // grid exactly covers NN
    float e1 = 1.f + eps[l];
    const uint4* hp4 = (const uint4*)(hprev + (size_t)n * HSTH);
    const float* ap = g_agg + (size_t)n * 32;

    float hf[HSTH];
#pragma unroll
    for (int q = 0; q < HSTH / 8; q++) {
        uint4 r = hp4[q];
        const __half2* h2 = (const __half2*)&r;
#pragma unroll
        for (int p = 0; p < 4; p++) {
            float2 f = __half22float2(h2[p]);
            int c = q * 8 + 2 * p;
            if (BNIN) {
                f.x = fmaxf(fmaf(f.x, shA[c], shB[c]), 0.f);
                f.y = fmaxf(fmaf(f.y, shA[c + 1], shB[c + 1]), 0.f);
            }
            hf[c + 0] = f.x;
            hf[c + 1] = f.y;
        }
    }

    float z[K];
#pragma unroll
    for (int k = 0; k < K; k += 4) {
        float4 a4 = *(const float4*)(ap + k);
        z[k + 0] = fmaf(e1, hf[k + 0], a4.x);
        z[k + 1] = fmaf(e1, hf[k + 1], a4.y);
        z[k + 2] = fmaf(e1, hf[k + 2], a4.z);
        z[k + 3] = fmaf(e1, hf[k + 3], a4.w);
    }

    ull u2[16];
    const ull* b1p = (const ull*)sb1;
#pragma unroll
    for (int jj = 0; jj < 16; jj++) u2[jj] = b1p[jj];
#pragma unroll
    for (int k = 0; k < K; k++) {
        ull zz = pk2(z[k], z[k]);
        const ulonglong2* w = (const ulonglong2*)&sW1[k << 5];
#pragma unroll
        for (int jj = 0; jj < 8; jj++) {
            ulonglong2 wv = w[jj];
            u2[2 * jj + 0] = fma2(zz, wv.x, u2[2 * jj + 0]);
            u2[2 * jj + 1] = fma2(zz, wv.y, u2[2 * jj + 1]);
        }
    }
    float u[32];
#pragma unroll
    for (int jj = 0; jj < 16; jj++) upk2(u2[jj], u[2 * jj], u[2 * jj + 1]);
#pragma unroll
    for (int j = 0; j < 32; j++) u[j] = fmaxf(u[j], 0.f);

    ull v2[16];
    const ull* b2p = (const ull*)sb2;
#pragma unroll
    for (int jj = 0; jj < 16; jj++) v2[jj] = b2p[jj];
#pragma unroll
    for (int k = 0; k < 32; k++) {
        ull uu = pk2(u[k], u[k]);
        const ulonglong2* w = (const ulonglong2*)&sW2[k << 5];
#pragma unroll
        for (int jj = 0; jj < 8; jj++) {
            ulonglong2 wv = w[jj];
            v2[2 * jj + 0] = fma2(uu, wv.x, v2[2 * jj + 0]);
            v2[2 * jj + 1] = fma2(uu, wv.y, v2[2 * jj + 1]);
        }
    }

    float vv[32];
#pragma unroll
    for (int jj = 0; jj < 16; jj++) upk2(v2[jj], vv[2 * jj], vv[2 * jj + 1]);

    // write z as half: 32 halfs = 64 bytes = 4 uint4 (R15 bug: was 2)
    uint4 outv[4];
    __half2* oh = (__half2*)outv;
#pragma unroll
    for (int q = 0; q < 16; q++) oh[q] = __floats2half2_rn(vv[2 * q], vv[2 * q + 1]);
    uint4* zp = (uint4*)(&g_zl[l][(size_t)n * 32]);
#pragma unroll
    for (int q = 0; q < 4; q++) zp[q] = outv[q];

    // fused BN stats (fp32, shfl butterfly per channel, constant indices)
    int lane = tid & 31;
    float mysum = 0.f, mysq = 0.f;
#pragma unroll
    for (int c = 0; c < 32; c++) {
        float s = vv[c];
        float q = s * s;
#pragma unroll
        for (int off = 16; off > 0; off >>= 1) {
            s += __shfl_xor_sync(0xFFFFFFFFu, s, off);
            q += __shfl_xor_sync(0xFFFFFFFFu, q, off);
        }
        if (lane == c) { mysum = s; mysq = q; }
    }
    atomicAdd(&ss2[lane], mysum);
    atomicAdd(&sq2[lane], mysq);
    __syncthreads();
    if (tid < 32) {
        atomicAdd(&g_stats[l * 64 + tid], ss2[tid]);
        atomicAdd(&g_stats[l * 64 + 32 + tid], sq2[tid]);
    }
}

// ---------------------------------------------------------------------------
// final: BN all 4 layers inline from g_zl, JK-GEMM, masked write-back
// ---------------------------------------------------------------------------
__global__ void __launch_bounds__(128) k_bnfinal(
    const float* __restrict__ x,
    const float* __restrict__ gamma, const float* __restrict__ beta,
    const float* __restrict__ linW, const float* __restrict__ linb,
    const int* __restrict__ nmask, const int* __restrict__ emask,
    const int* __restrict__ ondp, const int* __restrict__ oedp,
    float* __restrict__ out)
{
    __shared__ float sW[128 * 8];
    __shared__ float sb[8];
    __shared__ float sA[128], sB[128];      // BN constants for 4 layers x 32 ch
    int tid = threadIdx.x;
    for (int i = tid; i < 1024; i += 128) sW[i] = linW[i];
    if (tid < 8) sb[tid] = linb[tid];
    {
        int l = tid >> 5, c = tid & 31;     // tid < 128 covers all
        const float inv = 1.0f / (float)NN;
        float mu = g_stats[l * 64 + c] * inv;
        float var = g_stats[l * 64 + 32 + c] * inv - mu * mu;
        float rs = rsqrtf(var + 1e-5f);
        float ga = gamma[l * 32 + c];
        sA[tid] = rs * ga;
        sB[tid] = beta[l * 32 + c] - mu * rs * ga;
    }
    __syncthreads();

    int n = blockIdx.x * 128 + tid;
    if (n >= NN) return;

    float acc[8];
#pragma unroll
    for (int j = 0; j < 8; j++) acc[j] = sb[j];
#pragma unroll
    for (int l = 0; l < 4; l++) {
        const uint4* cp4 = (const uint4*)(&g_zl[l][(size_t)n * 32]);
#pragma unroll
        for (int q = 0; q < 4; q++) {
            uint4 r = cp4[q];
            const __half2* h2 = (const __half2*)&r;
#pragma unroll
            for (int p = 0; p < 4; p++) {
                float2 f = __half22float2(h2[p]);
                int c = q * 8 + 2 * p;
                float cA = fmaxf(fmaf(f.x, sA[l * 32 + c], sB[l * 32 + c]), 0.f);
                float cB = fmaxf(fmaf(f.y, sA[l * 32 + c + 1], sB[l * 32 + c + 1]), 0.f);
                int kk = l * 32 + c;
                const float4* w0 = (const float4*)&sW[kk * 8];
                const float4* w1 = (const float4*)&sW[(kk + 1) * 8];
                float4 a0 = w0[0], b0 = w0[1], a1 = w1[0], b1 = w1[1];
                acc[0] = fmaf(cA, a0.x, acc[0]); acc[0] = fmaf(cB, a1.x, acc[0]);
                acc[1] = fmaf(cA, a0.y, acc[1]); acc[1] = fmaf(cB, a1.y, acc[1]);
                acc[2] = fmaf(cA, a0.z, acc[2]); acc[2] = fmaf(cB, a1.z, acc[2]);
                acc[3] = fmaf(cA, a0.w, acc[3]); acc[3] = fmaf(cB, a1.w, acc[3]);
                acc[4] = fmaf(cA, b0.x, acc[4]); acc[4] = fmaf(cB, b1.x, acc[4]);
                acc[5] = fmaf(cA, b0.y, acc[5]); acc[5] = fmaf(cB, b1.y, acc[5]);
                acc[6] = fmaf(cA, b0.z, acc[6]); acc[6] = fmaf(cB, b1.z, acc[6]);
                acc[7] = fmaf(cA, b0.w, acc[7]); acc[7] = fmaf(cB, b1.w, acc[7]);
            }
        }
    }

    int ond = ondp[0], oed = oedp[0];
    bool nm = nmask[n] != 0;
    bool em = emask[n] != 0;
#pragma unroll
    for (int j = 0; j < 8; j++) {
        bool take = (j >= 1) && ((nm && j < ond + 1) || (em && j < oed + 1));
        out[(size_t)n * 8 + j] = take ? acc[j] : x[(size_t)n * 8 + j];
    }
}

// ---------------------------------------------------------------------------
extern "C" void kernel_launch(void* const* d_in, const int* in_sizes, int n_in,
                              void* d_out, int out_size) {
    const float* x     = (const float*)d_in[0];
    const float* t     = (const float*)d_in[1];
    const int*   ei    = (const int*)d_in[2];
    const int*   nmask = (const int*)d_in[3];
    const int*   emask = (const int*)d_in[4];
    const int*   ondp  = (const int*)d_in[5];
    const int*   oedp  = (const int*)d_in[6];
    const float* W1f   = (const float*)d_in[7];
    const float* b1f   = (const float*)d_in[8];
    const float* W2f   = (const float*)d_in[9];
    const float* b2f   = (const float*)d_in[10];
    const float* W1r   = (const float*)d_in[11];
    const float* b1r   = (const float*)d_in[12];
    const float* W2r   = (const float*)d_in[13];
    const float* b2r   = (const float*)d_in[14];
    const float* eps   = (const float*)d_in[15];
    const float* gam   = (const float*)d_in[16];
    const float* bet   = (const float*)d_in[17];
    const float* linW  = (const float*)d_in[18];
    const float* linb  = (const float*)d_in[19];
    float* out = (float*)d_out;

    const int* src = ei;
    const int* dst = ei + NE;

    // CSR build (4 launches)
    k_initcount<<<NE / 256, 256>>>(x, t, dst);
    k_scan1<<<256, 1024>>>();
    k_scan3<<<NN / 256, 256>>>();
    k_fill<<<NE / 256, 256>>>(src, dst);

    __half* h0p;  cudaGetSymbolAddress((void**)&h0p, g_h0);
    __half* zlp;  cudaGetSymbolAddress((void**)&zlp, g_zl);

    // layer 0 (h0 stride 16 halfs = 32B rows; no BN on input)
    k_gatherH<1, 16, false><<<(NN * 2) / 256, 256>>>(h0p, gam, bet, 0);
    k_node<12, 9, 16, false><<<NN / 128, 128>>>(h0p, W1f, b1f, W2f, b2f,
                                                eps, gam, bet, 0);

    // layers 1..3 (read g_zl[l-1] with inline BN+ReLU)
    for (int l = 1; l < 4; l++) {
        const __half* zprev = zlp + (size_t)(l - 1) * NN * 32;
        k_gatherH<2, 32, true><<<(NN * 4) / 256, 256>>>(zprev, gam, bet, l - 1);
        k_node<32, 32, 32, true><<<NN / 128, 128>>>(zprev,
                                                    W1r + (l - 1) * 1024, b1r + (l - 1) * 32,
                                                    W2r + (l - 1) * 1024, b2r + (l - 1) * 32,
                                                    eps, gam, bet, l);
    }

    k_bnfinal<<<NN / 128, 128>>>(x, gam, bet, linW, linb,
                                 nmask, emask, ondp, oedp, out);
}